// round 8
// baseline (speedup 1.0000x reference)
#include <cuda_runtime.h>
#include <cuda_fp16.h>
#include <cstdint>

// ============================================================================
// FreqLinear via mma.sync fp16 (single limb, scaled x256).
//
//   out[m,o] = (1/256) * sum_K (256*Y'[m,K]) * idx_f[o,K] + const[m] + bias[o]
//
// GEMM: CTA tile 128(o) x 128(m), K chunks of 64, 16 warps (4x4), warptile
// 32x32, mma.m16n8k16.f32.f16.f16.f32.
// R8: 3-stage smem pipeline (distance-2 cp.async B, distance-2 LDG A),
// wait_group 1 (no drain of in-flight group), fragment double-buffering
// inside the s-loop.
// ============================================================================

// ---------------- constants ----------------
static constexpr int IN_F   = 4096;
static constexpr int OUT_F  = 8192;
static constexpr int MROWS  = 256;
static constexpr int KTOT   = 2048;
static constexpr int K_CHUNK = 64;
static constexpr int NITER  = KTOT / K_CHUNK;   // 32
static constexpr int M_TILE = 128;
static constexpr int N_TILE = 128;

// smem: 3-stage A (3x16KB) + 3-stage B (3x16KB) = 96KB, then const/bias.
// Epilogue staging (128 x 132 f32 = 67.6KB) reuses the pipeline area.
#define SM_A(b)   ((b) * 16384)
#define SM_B(b)   (49152 + (b) * 16384)
#define SM_CONST  98304
#define SM_BIAS   98816
static constexpr int SMEM_TOTAL = 99360;

#define SWZ(o) ((o) ^ (((o) >> 3) & 0x70))  // SW128

// ---------------- scratch ----------------
__device__ __align__(16) __half g_Yh[MROWS * KTOT];  // 1 MB, holds 256*Y'
__device__ float g_const[MROWS];

// ---------------- asm helpers ----------------
__device__ __forceinline__ uint32_t smem_to_u32(const void* p) {
    uint32_t a;
    asm("{ .reg .u64 t; cvta.to.shared.u64 t, %1; cvt.u32.u64 %0, t; }" : "=r"(a) : "l"(p));
    return a;
}

__device__ __forceinline__ void ldmatrix_x4(uint32_t* r, uint32_t addr) {
    asm volatile("ldmatrix.sync.aligned.m8n8.x4.shared.b16 {%0,%1,%2,%3}, [%4];"
                 : "=r"(r[0]), "=r"(r[1]), "=r"(r[2]), "=r"(r[3]) : "r"(addr));
}

__device__ __forceinline__ void mma_16816(float* d, const uint32_t* a,
                                          uint32_t b0, uint32_t b1) {
    asm volatile(
        "mma.sync.aligned.m16n8k16.row.col.f32.f16.f16.f32 "
        "{%0,%1,%2,%3}, {%4,%5,%6,%7}, {%8,%9}, {%0,%1,%2,%3};"
        : "+f"(d[0]), "+f"(d[1]), "+f"(d[2]), "+f"(d[3])
        : "r"(a[0]), "r"(a[1]), "r"(a[2]), "r"(a[3]), "r"(b0), "r"(b1));
}

__device__ __forceinline__ void cp_async16(uint32_t smem_addr, const void* gptr) {
    asm volatile("cp.async.cg.shared.global [%0], [%1], 16;"
                 :: "r"(smem_addr), "l"(gptr) : "memory");
}
#define CP_COMMIT() asm volatile("cp.async.commit_group;" ::: "memory")
#define CP_WAIT_1() asm volatile("cp.async.wait_group 1;" ::: "memory")
#define CP_WAIT_0() asm volatile("cp.async.wait_group 0;" ::: "memory")

__device__ __forceinline__ uint32_t pack_fp16_pair(int a, int b) {
    uint32_t l = (uint32_t)__half_as_ushort(__float2half_rn((float)a));
    uint32_t h = (uint32_t)__half_as_ushort(__float2half_rn((float)b));
    return l | (h << 16);
}

// ---------------- Kernel 1: DCT of x, fp16 (x256), c_min constant -----------
__global__ __launch_bounds__(256, 1) void freql_prep_kernel(
    const float* __restrict__ x, const float* __restrict__ c_min,
    const float* __restrict__ c_range) {
    __shared__ float xs[IN_F];
    __shared__ float Bsm[8][16];
    __shared__ float warp_red[8];

    const int m = blockIdx.x;
    const int tid = threadIdx.x;

    for (int i = tid; i < IN_F; i += 256) xs[i] = x[(size_t)m * IN_F + i];
    if (tid < 128) {
        int k = tid >> 4, j = tid & 15;
        float s = (k == 0) ? 0.25f : 0.35355339059327373f;
        Bsm[k][j] = cospif((j + 0.5f) * (float)k * (1.0f / 16.0f)) * s;
    }
    __syncthreads();

    const int blk = tid;
    float acc[8];
#pragma unroll
    for (int k = 0; k < 8; k++) acc[k] = 0.0f;
#pragma unroll
    for (int j = 0; j < 16; j++) {
        float xv = xs[blk * 16 + j];
#pragma unroll
        for (int k = 0; k < 8; k++) acc[k] += xv * Bsm[k][j];
    }

    float cmv[8], crv[8];
#pragma unroll
    for (int k = 0; k < 8; k++) { cmv[k] = c_min[k]; crv[k] = c_range[k]; }

    float cst = 0.0f;
    struct alignas(16) H8 { __half h[8]; };
    H8 hv;
#pragma unroll
    for (int k = 0; k < 8; k++) {
        cst += cmv[k] * acc[k];
        float v = acc[k] * (crv[k] * (256.0f / 255.0f));
        hv.h[k] = __float2half_rn(v);
    }
    *(uint4*)&g_Yh[(size_t)m * KTOT + blk * 8] = *(uint4*)&hv;

#pragma unroll
    for (int s = 16; s > 0; s >>= 1) cst += __shfl_down_sync(0xFFFFFFFFu, cst, s);
    if ((tid & 31) == 0) warp_red[tid >> 5] = cst;
    __syncthreads();
    if (tid == 0) {
        float t = 0.0f;
#pragma unroll
        for (int w = 0; w < 8; w++) t += warp_red[w];
        g_const[m] = t;
    }
}

// ---------------- Kernel 2: fp16 mma.sync GEMM ----------------
__global__ __launch_bounds__(512, 1) void freql_gemm_kernel(
    const int* __restrict__ idx, const float* __restrict__ bias,
    float* __restrict__ out) {
    extern __shared__ char smem[];
    const uint32_t sa = smem_to_u32(smem);
    const int tid = threadIdx.x;
    const int wid = tid >> 5;
    const int lid = tid & 31;
    const int wo = wid & 3;
    const int wm = wid >> 2;
    const int o_base = blockIdx.x * M_TILE;
    const int m_base = blockIdx.y * N_TILE;

    if (tid < 128) {
        ((float*)(smem + SM_CONST))[tid] = g_const[m_base + tid];
        ((float*)(smem + SM_BIAS))[tid] = __ldg(bias + o_base + tid);
    }

    const int* arow = idx + (size_t)o_base * KTOT;

    // chunk mapping: chunk = tid + q*512 (q=0,1) -> row r=chunk>>3, 16B col c8=chunk&7
    int4 va[4];

    auto ldgA = [&](int it) {
        const int kb = it * K_CHUNK;
#pragma unroll
        for (int q = 0; q < 2; q++) {
            int chunk = tid + q * 512;
            int r = chunk >> 3, c8 = chunk & 7;
            const int4* s = (const int4*)(arow + (size_t)r * KTOT + kb + c8 * 8);
            va[q * 2] = s[0];
            va[q * 2 + 1] = s[1];
        }
    };
    auto stsA = [&](int buf) {
#pragma unroll
        for (int q = 0; q < 2; q++) {
            int chunk = tid + q * 512;
            int r = chunk >> 3, c8 = chunk & 7;
            uint4 p;
            p.x = pack_fp16_pair(va[q * 2].x, va[q * 2].y);
            p.y = pack_fp16_pair(va[q * 2].z, va[q * 2].w);
            p.z = pack_fp16_pair(va[q * 2 + 1].x, va[q * 2 + 1].y);
            p.w = pack_fp16_pair(va[q * 2 + 1].z, va[q * 2 + 1].w);
            uint32_t off = (uint32_t)(r * 128 + c8 * 16);
            *(uint4*)(smem + SM_A(buf) + SWZ(off)) = p;
        }
    };
    auto cpB = [&](int it, int buf) {
        const int kb = it * K_CHUNK;
#pragma unroll
        for (int q = 0; q < 2; q++) {
            int chunk = tid + q * 512;
            int r = chunk >> 3, c8 = chunk & 7;
            uint32_t off = SWZ((uint32_t)(r * 128 + c8 * 16));
            size_t g = (size_t)(m_base + r) * KTOT + kb + c8 * 8;
            cp_async16(sa + SM_B(buf) + off, g_Yh + g);
        }
    };

    float acc[2][4][4];
#pragma unroll
    for (int i = 0; i < 2; i++)
#pragma unroll
        for (int j = 0; j < 4; j++)
#pragma unroll
            for (int c = 0; c < 4; c++) acc[i][j][c] = 0.0f;

    const int a_row = lid & 15;
    const int a_cb  = (lid >> 4) * 16;
    const int b_row = (lid & 7) + ((lid >> 4) << 3);
    const int b_cb  = ((lid >> 3) & 1) * 16;

    // -------- prologue: stage 0 and 1 --------
    ldgA(0);
    cpB(0, 0); CP_COMMIT();
    stsA(0);
    ldgA(1);
    cpB(1, 1); CP_COMMIT();
    CP_WAIT_1();          // B buf0 complete (buf1 may fly)
    __syncthreads();      // A buf0 visible

    for (int it = 0; it < NITER; ++it) {
        const int cur = it % 3;
        const bool pf2 = (it + 2 < NITER);

        // prefetches for it+2 / finish staging it+1
        if (pf2) { cpB(it + 2, (it + 2) % 3); CP_COMMIT(); }
        if (it + 1 < NITER) stsA((it + 1) % 3);   // consumes va (loaded last iter)
        if (pf2) ldgA(it + 2);                    // refill va for next iter's stsA

        // -------- compute on buffer cur, fragments double-buffered --------
        const uint32_t abase = sa + SM_A(cur);
        const uint32_t bbase = sa + SM_B(cur);
        uint32_t afr[2][2][4], bfr[2][2][4];

#pragma unroll
        for (int mt = 0; mt < 2; mt++)
            ldmatrix_x4(afr[0][mt], abase + SWZ((uint32_t)((wo * 32 + mt * 16 + a_row) * 128 + a_cb)));
#pragma unroll
        for (int ng = 0; ng < 2; ng++)
            ldmatrix_x4(bfr[0][ng], bbase + SWZ((uint32_t)((wm * 32 + ng * 16 + b_row) * 128 + b_cb)));

#pragma unroll
        for (int s = 0; s < 4; s++) {
            const int pb = s & 1;
            if (s < 3) {
                const int nb = pb ^ 1;
#pragma unroll
                for (int mt = 0; mt < 2; mt++)
                    ldmatrix_x4(afr[nb][mt],
                        abase + SWZ((uint32_t)((wo * 32 + mt * 16 + a_row) * 128 + (s + 1) * 32 + a_cb)));
#pragma unroll
                for (int ng = 0; ng < 2; ng++)
                    ldmatrix_x4(bfr[nb][ng],
                        bbase + SWZ((uint32_t)((wm * 32 + ng * 16 + b_row) * 128 + (s + 1) * 32 + b_cb)));
            }
#pragma unroll
            for (int ng = 0; ng < 2; ng++) {
#pragma unroll
                for (int mt = 0; mt < 2; mt++) {
                    mma_16816(acc[mt][ng * 2 + 0], afr[pb][mt], bfr[pb][ng][0], bfr[pb][ng][1]);
                    mma_16816(acc[mt][ng * 2 + 1], afr[pb][mt], bfr[pb][ng][2], bfr[pb][ng][3]);
                }
            }
        }

        // buffer (it+1)%3's B must be complete; (it+2)%3's group may fly
        if (it + 1 < NITER) {
            if (pf2) CP_WAIT_1(); else CP_WAIT_0();
            __syncthreads();
        }
    }

    // -------- epilogue: stage (acc/256 + const[m]) to smem, float4 stores ----
    __syncthreads();
    {
        const float* scst = (const float*)(smem + SM_CONST);
        float* stg = (float*)smem;
        const int t4 = lid >> 2;
        const float inv256 = 1.0f / 256.0f;
#pragma unroll
        for (int mt = 0; mt < 2; mt++) {
#pragma unroll
            for (int nidx = 0; nidx < 4; nidx++) {
#pragma unroll
                for (int c = 0; c < 4; c++) {
                    int o = wo * 32 + mt * 16 + ((c >> 1) << 3) + t4;
                    int mm = wm * 32 + nidx * 8 + (lid & 3) * 2 + (c & 1);
                    stg[mm * 132 + o] = acc[mt][nidx][c] * inv256 + scst[mm];
                }
            }
        }
    }
    __syncthreads();
    {
        const float* stg = (const float*)smem;
        const float* sbias = (const float*)(smem + SM_BIAS);
        const int o4 = (tid & 31) * 4;
        float4 bv;
        bv.x = sbias[o4]; bv.y = sbias[o4 + 1]; bv.z = sbias[o4 + 2]; bv.w = sbias[o4 + 3];
#pragma unroll
        for (int p = 0; p < 8; p++) {
            int mm = p * 16 + (tid >> 5);
            float4 v = *(const float4*)(stg + mm * 132 + o4);
            v.x += bv.x; v.y += bv.y; v.z += bv.z; v.w += bv.w;
            *(float4*)(out + (size_t)(m_base + mm) * OUT_F + o_base + o4) = v;
        }
    }
}

// ---------------- launch ----------------
extern "C" void kernel_launch(void* const* d_in, const int* in_sizes, int n_in,
                              void* d_out, int out_size) {
    const float* x       = (const float*)d_in[0];
    const int*   idx     = (const int*)d_in[1];
    const float* c_min   = (const float*)d_in[2];
    const float* c_range = (const float*)d_in[3];
    const float* bias    = (const float*)d_in[4];
    float* out = (float*)d_out;

    cudaFuncSetAttribute(freql_gemm_kernel,
                         cudaFuncAttributeMaxDynamicSharedMemorySize, SMEM_TOTAL);

    freql_prep_kernel<<<MROWS, 256>>>(x, c_min, c_range);
    freql_gemm_kernel<<<dim3(OUT_F / M_TILE, MROWS / N_TILE), 512, SMEM_TOTAL>>>(idx, bias, out);
}

// round 9
// speedup vs baseline: 1.1733x; 1.1733x over previous
#include <cuda_runtime.h>
#include <cuda_fp16.h>
#include <cstdint>

// ============================================================================
// FreqLinear via mma.sync fp16 (single limb, scaled x256).
//
//   out[m,o] = (1/256) * sum_K (256*Y'[m,K]) * idx_f[o,K] + const[m] + bias[o]
//
// GEMM: CTA tile 128(o) x 128(m), 16 warps (4x4), warptile 32x32,
// mma.m16n8k16.f32.f16.f16.f32. R9: K_CHUNK=128 two-stage pipeline
// (16 iterations, half the barriers of R7); A staged in two K64 halves
// interleaved into the compute block to keep register pressure flat.
// ============================================================================

// ---------------- constants ----------------
static constexpr int IN_F   = 4096;
static constexpr int OUT_F  = 8192;
static constexpr int MROWS  = 256;
static constexpr int KTOT   = 2048;
static constexpr int K_CHUNK = 128;
static constexpr int NITER  = KTOT / K_CHUNK;   // 16
static constexpr int M_TILE = 128;
static constexpr int N_TILE = 128;

// smem: A 2x32KB + B 2x32KB = 128KB pipeline, + const/bias.
// Epilogue staging (128 x 132 f32 = 67.6KB) reuses the pipeline area.
#define SM_A(b)   ((b) * 32768)
#define SM_B(b)   (65536 + (b) * 32768)
#define SM_CONST  131072
#define SM_BIAS   131584
static constexpr int SMEM_TOTAL = 132128;

#define SWZ(o) ((o) ^ (((o) >> 3) & 0x70))  // SW128

// ---------------- scratch ----------------
__device__ __align__(16) __half g_Yh[MROWS * KTOT];  // 1 MB, holds 256*Y'
__device__ float g_const[MROWS];

// ---------------- asm helpers ----------------
__device__ __forceinline__ uint32_t smem_to_u32(const void* p) {
    uint32_t a;
    asm("{ .reg .u64 t; cvta.to.shared.u64 t, %1; cvt.u32.u64 %0, t; }" : "=r"(a) : "l"(p));
    return a;
}

__device__ __forceinline__ void ldmatrix_x4(uint32_t* r, uint32_t addr) {
    asm volatile("ldmatrix.sync.aligned.m8n8.x4.shared.b16 {%0,%1,%2,%3}, [%4];"
                 : "=r"(r[0]), "=r"(r[1]), "=r"(r[2]), "=r"(r[3]) : "r"(addr));
}

__device__ __forceinline__ void mma_16816(float* d, const uint32_t* a,
                                          uint32_t b0, uint32_t b1) {
    asm volatile(
        "mma.sync.aligned.m16n8k16.row.col.f32.f16.f16.f32 "
        "{%0,%1,%2,%3}, {%4,%5,%6,%7}, {%8,%9}, {%0,%1,%2,%3};"
        : "+f"(d[0]), "+f"(d[1]), "+f"(d[2]), "+f"(d[3])
        : "r"(a[0]), "r"(a[1]), "r"(a[2]), "r"(a[3]), "r"(b0), "r"(b1));
}

__device__ __forceinline__ void cp_async16(uint32_t smem_addr, const void* gptr) {
    asm volatile("cp.async.cg.shared.global [%0], [%1], 16;"
                 :: "r"(smem_addr), "l"(gptr) : "memory");
}
#define CP_COMMIT() asm volatile("cp.async.commit_group;" ::: "memory")
#define CP_WAIT_0() asm volatile("cp.async.wait_group 0;" ::: "memory")

__device__ __forceinline__ uint32_t pack_fp16_pair(int a, int b) {
    uint32_t l = (uint32_t)__half_as_ushort(__float2half_rn((float)a));
    uint32_t h = (uint32_t)__half_as_ushort(__float2half_rn((float)b));
    return l | (h << 16);
}

// ---------------- Kernel 1: DCT of x, fp16 (x256), c_min constant -----------
__global__ __launch_bounds__(256, 1) void freql_prep_kernel(
    const float* __restrict__ x, const float* __restrict__ c_min,
    const float* __restrict__ c_range) {
    __shared__ float xs[IN_F];
    __shared__ float Bsm[8][16];
    __shared__ float warp_red[8];

    const int m = blockIdx.x;
    const int tid = threadIdx.x;

    for (int i = tid; i < IN_F; i += 256) xs[i] = x[(size_t)m * IN_F + i];
    if (tid < 128) {
        int k = tid >> 4, j = tid & 15;
        float s = (k == 0) ? 0.25f : 0.35355339059327373f;
        Bsm[k][j] = cospif((j + 0.5f) * (float)k * (1.0f / 16.0f)) * s;
    }
    __syncthreads();

    const int blk = tid;
    float acc[8];
#pragma unroll
    for (int k = 0; k < 8; k++) acc[k] = 0.0f;
#pragma unroll
    for (int j = 0; j < 16; j++) {
        float xv = xs[blk * 16 + j];
#pragma unroll
        for (int k = 0; k < 8; k++) acc[k] += xv * Bsm[k][j];
    }

    float cmv[8], crv[8];
#pragma unroll
    for (int k = 0; k < 8; k++) { cmv[k] = c_min[k]; crv[k] = c_range[k]; }

    float cst = 0.0f;
    struct alignas(16) H8 { __half h[8]; };
    H8 hv;
#pragma unroll
    for (int k = 0; k < 8; k++) {
        cst += cmv[k] * acc[k];
        float v = acc[k] * (crv[k] * (256.0f / 255.0f));
        hv.h[k] = __float2half_rn(v);
    }
    *(uint4*)&g_Yh[(size_t)m * KTOT + blk * 8] = *(uint4*)&hv;

#pragma unroll
    for (int s = 16; s > 0; s >>= 1) cst += __shfl_down_sync(0xFFFFFFFFu, cst, s);
    if ((tid & 31) == 0) warp_red[tid >> 5] = cst;
    __syncthreads();
    if (tid == 0) {
        float t = 0.0f;
#pragma unroll
        for (int w = 0; w < 8; w++) t += warp_red[w];
        g_const[m] = t;
    }
}

// ---------------- Kernel 2: fp16 mma.sync GEMM ----------------
__global__ __launch_bounds__(512, 1) void freql_gemm_kernel(
    const int* __restrict__ idx, const float* __restrict__ bias,
    float* __restrict__ out) {
    extern __shared__ char smem[];
    const uint32_t sa = smem_to_u32(smem);
    const int tid = threadIdx.x;
    const int wid = tid >> 5;
    const int lid = tid & 31;
    const int wo = wid & 3;
    const int wm = wid >> 2;
    const int o_base = blockIdx.x * M_TILE;
    const int m_base = blockIdx.y * N_TILE;

    if (tid < 128) {
        ((float*)(smem + SM_CONST))[tid] = g_const[m_base + tid];
        ((float*)(smem + SM_BIAS))[tid] = __ldg(bias + o_base + tid);
    }

    const int* arow = idx + (size_t)o_base * KTOT;

    // chunk mapping: chunk = tid + q*512 (q=0,1) -> row r=chunk>>3, 16B col c8=chunk&7
    int4 va[4];

    // load one K64 half of the A source (idx) into registers
    auto ldgA = [&](int it, int h) {
        const int kb = it * K_CHUNK + h * 64;
#pragma unroll
        for (int q = 0; q < 2; q++) {
            int chunk = tid + q * 512;
            int r = chunk >> 3, c8 = chunk & 7;
            const int4* s = (const int4*)(arow + (size_t)r * KTOT + kb + c8 * 8);
            va[q * 2] = s[0];
            va[q * 2 + 1] = s[1];
        }
    };
    // convert + store one K64 half into sub-tile h of buffer buf
    auto stsA = [&](int buf, int h) {
        const uint32_t base = (buf ? SM_A(1) : SM_A(0)) + (uint32_t)h * 16384;
#pragma unroll
        for (int q = 0; q < 2; q++) {
            int chunk = tid + q * 512;
            int r = chunk >> 3, c8 = chunk & 7;
            uint4 p;
            p.x = pack_fp16_pair(va[q * 2].x, va[q * 2].y);
            p.y = pack_fp16_pair(va[q * 2].z, va[q * 2].w);
            p.z = pack_fp16_pair(va[q * 2 + 1].x, va[q * 2 + 1].y);
            p.w = pack_fp16_pair(va[q * 2 + 1].z, va[q * 2 + 1].w);
            uint32_t off = (uint32_t)(r * 128 + c8 * 16);
            *(uint4*)(smem + base + SWZ(off)) = p;
        }
    };
    // cp.async the full K128 B tile (both halves) into buffer buf
    auto cpB = [&](int it, int buf) {
#pragma unroll
        for (int h = 0; h < 2; h++) {
            const int kb = it * K_CHUNK + h * 64;
            const uint32_t base = sa + (buf ? SM_B(1) : SM_B(0)) + (uint32_t)h * 16384;
#pragma unroll
            for (int q = 0; q < 2; q++) {
                int chunk = tid + q * 512;
                int r = chunk >> 3, c8 = chunk & 7;
                uint32_t off = SWZ((uint32_t)(r * 128 + c8 * 16));
                size_t g = (size_t)(m_base + r) * KTOT + kb + c8 * 8;
                cp_async16(base + off, g_Yh + g);
            }
        }
    };

    float acc[2][4][4];
#pragma unroll
    for (int i = 0; i < 2; i++)
#pragma unroll
        for (int j = 0; j < 4; j++)
#pragma unroll
            for (int c = 0; c < 4; c++) acc[i][j][c] = 0.0f;

    const int a_row = lid & 15;
    const int a_cb  = (lid >> 4) * 16;
    const int b_row = (lid & 7) + ((lid >> 4) << 3);
    const int b_cb  = ((lid >> 3) & 1) * 16;

    // compute 4 s-steps on one K64 sub-tile
    auto compute_half = [&](uint32_t abase, uint32_t bbase) {
#pragma unroll
        for (int s = 0; s < 4; s++) {
            uint32_t afr[2][4];
#pragma unroll
            for (int mt = 0; mt < 2; mt++)
                ldmatrix_x4(afr[mt],
                    abase + SWZ((uint32_t)((wo * 32 + mt * 16 + a_row) * 128 + s * 32 + a_cb)));
#pragma unroll
            for (int ng = 0; ng < 2; ng++) {
                uint32_t bfr[4];
                ldmatrix_x4(bfr,
                    bbase + SWZ((uint32_t)((wm * 32 + ng * 16 + b_row) * 128 + s * 32 + b_cb)));
#pragma unroll
                for (int mt = 0; mt < 2; mt++) {
                    mma_16816(acc[mt][ng * 2 + 0], afr[mt], bfr[0], bfr[1]);
                    mma_16816(acc[mt][ng * 2 + 1], afr[mt], bfr[2], bfr[3]);
                }
            }
        }
    };

    // -------- prologue: fully stage buffer 0 --------
    cpB(0, 0); CP_COMMIT();
    ldgA(0, 0); stsA(0, 0);
    ldgA(0, 1); stsA(0, 1);
    CP_WAIT_0();
    __syncthreads();

    for (int it = 0; it < NITER; ++it) {
        const int cur = it & 1, nxt = cur ^ 1;
        const bool pf = (it + 1 < NITER);

        if (pf) {
            cpB(it + 1, nxt); CP_COMMIT();
            ldgA(it + 1, 0);
        }

        // compute first K64 half of cur
        compute_half(sa + (cur ? SM_A(1) : SM_A(0)),
                     sa + (cur ? SM_B(1) : SM_B(0)));

        if (pf) {
            stsA(nxt, 0);
            ldgA(it + 1, 1);
        }

        // compute second K64 half of cur
        compute_half(sa + (cur ? SM_A(1) : SM_A(0)) + 16384,
                     sa + (cur ? SM_B(1) : SM_B(0)) + 16384);

        if (pf) {
            stsA(nxt, 1);
            CP_WAIT_0();
            __syncthreads();
        }
    }

    // -------- epilogue: stage (acc/256 + const[m]) to smem, float4 stores ----
    __syncthreads();
    {
        const float* scst = (const float*)(smem + SM_CONST);
        float* stg = (float*)smem;
        const int t4 = lid >> 2;
        const float inv256 = 1.0f / 256.0f;
#pragma unroll
        for (int mt = 0; mt < 2; mt++) {
#pragma unroll
            for (int nidx = 0; nidx < 4; nidx++) {
#pragma unroll
                for (int c = 0; c < 4; c++) {
                    int o = wo * 32 + mt * 16 + ((c >> 1) << 3) + t4;
                    int mm = wm * 32 + nidx * 8 + (lid & 3) * 2 + (c & 1);
                    stg[mm * 132 + o] = acc[mt][nidx][c] * inv256 + scst[mm];
                }
            }
        }
    }
    __syncthreads();
    {
        const float* stg = (const float*)smem;
        const float* sbias = (const float*)(smem + SM_BIAS);
        const int o4 = (tid & 31) * 4;
        float4 bv;
        bv.x = sbias[o4]; bv.y = sbias[o4 + 1]; bv.z = sbias[o4 + 2]; bv.w = sbias[o4 + 3];
#pragma unroll
        for (int p = 0; p < 8; p++) {
            int mm = p * 16 + (tid >> 5);
            float4 v = *(const float4*)(stg + mm * 132 + o4);
            v.x += bv.x; v.y += bv.y; v.z += bv.z; v.w += bv.w;
            *(float4*)(out + (size_t)(m_base + mm) * OUT_F + o_base + o4) = v;
        }
    }
}

// ---------------- launch ----------------
extern "C" void kernel_launch(void* const* d_in, const int* in_sizes, int n_in,
                              void* d_out, int out_size) {
    const float* x       = (const float*)d_in[0];
    const int*   idx     = (const int*)d_in[1];
    const float* c_min   = (const float*)d_in[2];
    const float* c_range = (const float*)d_in[3];
    const float* bias    = (const float*)d_in[4];
    float* out = (float*)d_out;

    cudaFuncSetAttribute(freql_gemm_kernel,
                         cudaFuncAttributeMaxDynamicSharedMemorySize, SMEM_TOTAL);

    freql_prep_kernel<<<MROWS, 256>>>(x, c_min, c_range);
    freql_gemm_kernel<<<dim3(OUT_F / M_TILE, MROWS / N_TILE), 512, SMEM_TOTAL>>>(idx, bias, out);
}

// round 10
// speedup vs baseline: 1.2527x; 1.0677x over previous
#include <cuda_runtime.h>
#include <cuda_fp16.h>
#include <cstdint>

// ============================================================================
// FreqLinear via mma.sync fp16 (single limb, scaled x256).
//
//   out[m,o] = (1/256) * sum_K (256*Y'[m,K]) * idx_f[o,K] + const[m] + bias[o]
//
// R10: CTA tile 64(o) x 128(m), 8 warps (2x4), warptile 32x32, 256 threads,
// grid (128,2) = 256 CTAs -> 2 CTAs resident per SM (96KB smem, <=128 regs).
// K_CHUNK=128 two-stage pipeline with A staged in two K64 halves interleaved
// into the compute block (as R9).
// ============================================================================

// ---------------- constants ----------------
static constexpr int IN_F   = 4096;
static constexpr int OUT_F  = 8192;
static constexpr int MROWS  = 256;
static constexpr int KTOT   = 2048;
static constexpr int K_CHUNK = 128;
static constexpr int NITER  = KTOT / K_CHUNK;   // 16
static constexpr int M_TILE = 64;               // o per CTA
static constexpr int N_TILE = 128;              // m per CTA

// smem per CTA: A 2x16KB + B 2x32KB = 96KB pipeline, + const/bias.
// Epilogue staging (128 x 68 f32 = 34.8KB) reuses the pipeline area.
#define SM_A(b)   ((b) * 16384)
#define SM_B(b)   (32768 + (b) * 32768)
#define SM_CONST  98304
#define SM_BIAS   98816
static constexpr int SMEM_TOTAL = 99072;

#define SWZ(o) ((o) ^ (((o) >> 3) & 0x70))  // SW128

// ---------------- scratch ----------------
__device__ __align__(16) __half g_Yh[MROWS * KTOT];  // 1 MB, holds 256*Y'
__device__ float g_const[MROWS];

// ---------------- asm helpers ----------------
__device__ __forceinline__ uint32_t smem_to_u32(const void* p) {
    uint32_t a;
    asm("{ .reg .u64 t; cvta.to.shared.u64 t, %1; cvt.u32.u64 %0, t; }" : "=r"(a) : "l"(p));
    return a;
}

__device__ __forceinline__ void ldmatrix_x4(uint32_t* r, uint32_t addr) {
    asm volatile("ldmatrix.sync.aligned.m8n8.x4.shared.b16 {%0,%1,%2,%3}, [%4];"
                 : "=r"(r[0]), "=r"(r[1]), "=r"(r[2]), "=r"(r[3]) : "r"(addr));
}

__device__ __forceinline__ void mma_16816(float* d, const uint32_t* a,
                                          uint32_t b0, uint32_t b1) {
    asm volatile(
        "mma.sync.aligned.m16n8k16.row.col.f32.f16.f16.f32 "
        "{%0,%1,%2,%3}, {%4,%5,%6,%7}, {%8,%9}, {%0,%1,%2,%3};"
        : "+f"(d[0]), "+f"(d[1]), "+f"(d[2]), "+f"(d[3])
        : "r"(a[0]), "r"(a[1]), "r"(a[2]), "r"(a[3]), "r"(b0), "r"(b1));
}

__device__ __forceinline__ void cp_async16(uint32_t smem_addr, const void* gptr) {
    asm volatile("cp.async.cg.shared.global [%0], [%1], 16;"
                 :: "r"(smem_addr), "l"(gptr) : "memory");
}
#define CP_COMMIT() asm volatile("cp.async.commit_group;" ::: "memory")
#define CP_WAIT_0() asm volatile("cp.async.wait_group 0;" ::: "memory")

__device__ __forceinline__ uint32_t pack_fp16_pair(int a, int b) {
    uint32_t l = (uint32_t)__half_as_ushort(__float2half_rn((float)a));
    uint32_t h = (uint32_t)__half_as_ushort(__float2half_rn((float)b));
    return l | (h << 16);
}

// ---------------- Kernel 1: DCT of x, fp16 (x256), c_min constant -----------
__global__ __launch_bounds__(256, 1) void freql_prep_kernel(
    const float* __restrict__ x, const float* __restrict__ c_min,
    const float* __restrict__ c_range) {
    __shared__ float xs[IN_F];
    __shared__ float Bsm[8][16];
    __shared__ float warp_red[8];

    const int m = blockIdx.x;
    const int tid = threadIdx.x;

    for (int i = tid; i < IN_F; i += 256) xs[i] = x[(size_t)m * IN_F + i];
    if (tid < 128) {
        int k = tid >> 4, j = tid & 15;
        float s = (k == 0) ? 0.25f : 0.35355339059327373f;
        Bsm[k][j] = cospif((j + 0.5f) * (float)k * (1.0f / 16.0f)) * s;
    }
    __syncthreads();

    const int blk = tid;
    float acc[8];
#pragma unroll
    for (int k = 0; k < 8; k++) acc[k] = 0.0f;
#pragma unroll
    for (int j = 0; j < 16; j++) {
        float xv = xs[blk * 16 + j];
#pragma unroll
        for (int k = 0; k < 8; k++) acc[k] += xv * Bsm[k][j];
    }

    float cmv[8], crv[8];
#pragma unroll
    for (int k = 0; k < 8; k++) { cmv[k] = c_min[k]; crv[k] = c_range[k]; }

    float cst = 0.0f;
    struct alignas(16) H8 { __half h[8]; };
    H8 hv;
#pragma unroll
    for (int k = 0; k < 8; k++) {
        cst += cmv[k] * acc[k];
        float v = acc[k] * (crv[k] * (256.0f / 255.0f));
        hv.h[k] = __float2half_rn(v);
    }
    *(uint4*)&g_Yh[(size_t)m * KTOT + blk * 8] = *(uint4*)&hv;

#pragma unroll
    for (int s = 16; s > 0; s >>= 1) cst += __shfl_down_sync(0xFFFFFFFFu, cst, s);
    if ((tid & 31) == 0) warp_red[tid >> 5] = cst;
    __syncthreads();
    if (tid == 0) {
        float t = 0.0f;
#pragma unroll
        for (int w = 0; w < 8; w++) t += warp_red[w];
        g_const[m] = t;
    }
}

// ---------------- Kernel 2: fp16 mma.sync GEMM ----------------
__global__ __launch_bounds__(256, 2) void freql_gemm_kernel(
    const int* __restrict__ idx, const float* __restrict__ bias,
    float* __restrict__ out) {
    extern __shared__ char smem[];
    const uint32_t sa = smem_to_u32(smem);
    const int tid = threadIdx.x;
    const int wid = tid >> 5;
    const int lid = tid & 31;
    const int wo = wid & 1;          // warp o-tile (2 x 32)
    const int wm = wid >> 1;         // warp m-tile (4 x 32)
    const int o_base = blockIdx.x * M_TILE;
    const int m_base = blockIdx.y * N_TILE;

    if (tid < 128) ((float*)(smem + SM_CONST))[tid] = g_const[m_base + tid];
    if (tid < 64)  ((float*)(smem + SM_BIAS))[tid] = __ldg(bias + o_base + tid);

    const int* arow = idx + (size_t)o_base * KTOT;

    // A chunks (per K64 half): 64 rows x 128B = 512 x 16B chunks; q<2
    // B chunks (per K64 half): 128 rows x 128B = 1024 chunks; q<4
    int4 va[4];

    auto ldgA = [&](int it, int h) {
        const int kb = it * K_CHUNK + h * 64;
#pragma unroll
        for (int q = 0; q < 2; q++) {
            int chunk = tid + q * 256;
            int r = chunk >> 3, c8 = chunk & 7;
            const int4* s = (const int4*)(arow + (size_t)r * KTOT + kb + c8 * 8);
            va[q * 2] = s[0];
            va[q * 2 + 1] = s[1];
        }
    };
    auto stsA = [&](int buf, int h) {
        const uint32_t base = (buf ? SM_A(1) : SM_A(0)) + (uint32_t)h * 8192;
#pragma unroll
        for (int q = 0; q < 2; q++) {
            int chunk = tid + q * 256;
            int r = chunk >> 3, c8 = chunk & 7;
            uint4 p;
            p.x = pack_fp16_pair(va[q * 2].x, va[q * 2].y);
            p.y = pack_fp16_pair(va[q * 2].z, va[q * 2].w);
            p.z = pack_fp16_pair(va[q * 2 + 1].x, va[q * 2 + 1].y);
            p.w = pack_fp16_pair(va[q * 2 + 1].z, va[q * 2 + 1].w);
            uint32_t off = (uint32_t)(r * 128 + c8 * 16);
            *(uint4*)(smem + base + SWZ(off)) = p;
        }
    };
    auto cpB = [&](int it, int buf) {
#pragma unroll
        for (int h = 0; h < 2; h++) {
            const int kb = it * K_CHUNK + h * 64;
            const uint32_t base = sa + (buf ? SM_B(1) : SM_B(0)) + (uint32_t)h * 16384;
#pragma unroll
            for (int q = 0; q < 4; q++) {
                int chunk = tid + q * 256;
                int r = chunk >> 3, c8 = chunk & 7;
                uint32_t off = SWZ((uint32_t)(r * 128 + c8 * 16));
                size_t g = (size_t)(m_base + r) * KTOT + kb + c8 * 8;
                cp_async16(base + off, g_Yh + g);
            }
        }
    };

    float acc[2][4][4];
#pragma unroll
    for (int i = 0; i < 2; i++)
#pragma unroll
        for (int j = 0; j < 4; j++)
#pragma unroll
            for (int c = 0; c < 4; c++) acc[i][j][c] = 0.0f;

    const int a_row = lid & 15;
    const int a_cb  = (lid >> 4) * 16;
    const int b_row = (lid & 7) + ((lid >> 4) << 3);
    const int b_cb  = ((lid >> 3) & 1) * 16;

    auto compute_half = [&](uint32_t abase, uint32_t bbase) {
#pragma unroll
        for (int s = 0; s < 4; s++) {
            uint32_t afr[2][4];
#pragma unroll
            for (int mt = 0; mt < 2; mt++)
                ldmatrix_x4(afr[mt],
                    abase + SWZ((uint32_t)((wo * 32 + mt * 16 + a_row) * 128 + s * 32 + a_cb)));
#pragma unroll
            for (int ng = 0; ng < 2; ng++) {
                uint32_t bfr[4];
                ldmatrix_x4(bfr,
                    bbase + SWZ((uint32_t)((wm * 32 + ng * 16 + b_row) * 128 + s * 32 + b_cb)));
#pragma unroll
                for (int mt = 0; mt < 2; mt++) {
                    mma_16816(acc[mt][ng * 2 + 0], afr[mt], bfr[0], bfr[1]);
                    mma_16816(acc[mt][ng * 2 + 1], afr[mt], bfr[2], bfr[3]);
                }
            }
        }
    };

    // -------- prologue: fully stage buffer 0 --------
    cpB(0, 0); CP_COMMIT();
    ldgA(0, 0); stsA(0, 0);
    ldgA(0, 1); stsA(0, 1);
    CP_WAIT_0();
    __syncthreads();

    for (int it = 0; it < NITER; ++it) {
        const int cur = it & 1, nxt = cur ^ 1;
        const bool pf = (it + 1 < NITER);

        if (pf) {
            cpB(it + 1, nxt); CP_COMMIT();
            ldgA(it + 1, 0);
        }

        compute_half(sa + (cur ? SM_A(1) : SM_A(0)),
                     sa + (cur ? SM_B(1) : SM_B(0)));

        if (pf) {
            stsA(nxt, 0);
            ldgA(it + 1, 1);
        }

        compute_half(sa + (cur ? SM_A(1) : SM_A(0)) + 8192,
                     sa + (cur ? SM_B(1) : SM_B(0)) + 16384);

        if (pf) {
            stsA(nxt, 1);
            CP_WAIT_0();
            __syncthreads();
        }
    }

    // -------- epilogue: stage (acc/256 + const[m]) to smem [m][68], stores --
    __syncthreads();
    {
        const float* scst = (const float*)(smem + SM_CONST);
        float* stg = (float*)smem;
        const int t4 = lid >> 2;
        const float inv256 = 1.0f / 256.0f;
#pragma unroll
        for (int mt = 0; mt < 2; mt++) {
#pragma unroll
            for (int nidx = 0; nidx < 4; nidx++) {
#pragma unroll
                for (int c = 0; c < 4; c++) {
                    int o = wo * 32 + mt * 16 + ((c >> 1) << 3) + t4;
                    int mm = wm * 32 + nidx * 8 + (lid & 3) * 2 + (c & 1);
                    stg[mm * 68 + o] = acc[mt][nidx][c] * inv256 + scst[mm];
                }
            }
        }
    }
    __syncthreads();
    {
        const float* stg = (const float*)smem;
        const float* sbias = (const float*)(smem + SM_BIAS);
        const int o4 = (tid & 15) * 4;
        float4 bv;
        bv.x = sbias[o4]; bv.y = sbias[o4 + 1]; bv.z = sbias[o4 + 2]; bv.w = sbias[o4 + 3];
#pragma unroll
        for (int p = 0; p < 8; p++) {
            int mm = p * 16 + (tid >> 4);
            float4 v = *(const float4*)(stg + mm * 68 + o4);
            v.x += bv.x; v.y += bv.y; v.z += bv.z; v.w += bv.w;
            *(float4*)(out + (size_t)(m_base + mm) * OUT_F + o_base + o4) = v;
        }
    }
}

// ---------------- launch ----------------
extern "C" void kernel_launch(void* const* d_in, const int* in_sizes, int n_in,
                              void* d_out, int out_size) {
    const float* x       = (const float*)d_in[0];
    const int*   idx     = (const int*)d_in[1];
    const float* c_min   = (const float*)d_in[2];
    const float* c_range = (const float*)d_in[3];
    const float* bias    = (const float*)d_in[4];
    float* out = (float*)d_out;

    cudaFuncSetAttribute(freql_gemm_kernel,
                         cudaFuncAttributeMaxDynamicSharedMemorySize, SMEM_TOTAL);

    freql_prep_kernel<<<MROWS, 256>>>(x, c_min, c_range);
    freql_gemm_kernel<<<dim3(OUT_F / M_TILE, MROWS / N_TILE), 256, SMEM_TOTAL>>>(idx, bias, out);
}